// round 1
// baseline (speedup 1.0000x reference)
#include <cuda_runtime.h>
#include <cuda_bf16.h>

#define DD   128
#define NN   21845          // (4^8 - 1) / 3
#define NPOS 18
#define NDEP 46

// persistent scratch (device globals: allocation-free)
__device__ float g_xz[NN * DD];            // x, then z in-place per level
__device__ int   g_pos_perm[NN];
__device__ int   g_pos_off[NPOS + 1];
__device__ int   g_dep_perm[NN];           // per-level segments at child ranges
__device__ int   g_dep_off[7][NDEP + 1];   // [parent level l][group]

// ---------------------------------------------------------------------------
// Grouping: counting sort by matrix id, warp-aggregated shared atomics
// ---------------------------------------------------------------------------
__global__ void group_pos_kernel(const int* __restrict__ ids) {
    __shared__ int cnt[NPOS];
    __shared__ int off[NPOS + 1];
    int t = threadIdx.x;
    int lane = t & 31;
    if (t < NPOS) cnt[t] = 0;
    __syncthreads();
    int iters = (NN + blockDim.x - 1) / blockDim.x;
    for (int it = 0; it < iters; ++it) {
        int i = it * blockDim.x + t;
        bool valid = (i < NN);
        unsigned active = __ballot_sync(0xffffffffu, valid);
        if (valid) {
            int id = ids[i];
            unsigned m = __match_any_sync(active, id);
            int leader = __ffs(m) - 1;
            if (lane == leader) atomicAdd(&cnt[id], __popc(m));
        }
    }
    __syncthreads();
    if (t == 0) {
        int s = 0;
        for (int j = 0; j < NPOS; ++j) { off[j] = s; s += cnt[j]; }
        off[NPOS] = s;
        for (int j = 0; j <= NPOS; ++j) g_pos_off[j] = off[j];
    }
    __syncthreads();
    if (t < NPOS) cnt[t] = off[t];   // cursors
    __syncthreads();
    for (int it = 0; it < iters; ++it) {
        int i = it * blockDim.x + t;
        bool valid = (i < NN);
        unsigned active = __ballot_sync(0xffffffffu, valid);
        if (valid) {
            int id = ids[i];
            unsigned m = __match_any_sync(active, id);
            int leader = __ffs(m) - 1;
            int prior = __popc(m & ((1u << lane) - 1u));
            int basep = 0;
            if (lane == leader) basep = atomicAdd(&cnt[id], __popc(m));
            basep = __shfl_sync(active, basep, leader);
            g_pos_perm[basep + prior] = i;
        }
    }
}

__global__ void group_dep_kernel(const int* __restrict__ ids) {
    int l = blockIdx.x;                          // parent level 0..6
    int cs = ((1 << (2 * (l + 1))) - 1) / 3;     // child level start
    int n  = 1 << (2 * (l + 1));                 // child count
    __shared__ int cnt[NDEP];
    __shared__ int off[NDEP + 1];
    int t = threadIdx.x;
    int lane = t & 31;
    if (t < NDEP) cnt[t] = 0;
    __syncthreads();
    int iters = (n + blockDim.x - 1) / blockDim.x;
    for (int it = 0; it < iters; ++it) {
        int i = it * blockDim.x + t;
        bool valid = (i < n);
        unsigned active = __ballot_sync(0xffffffffu, valid);
        if (valid) {
            int id = ids[cs + i];
            unsigned m = __match_any_sync(active, id);
            int leader = __ffs(m) - 1;
            if (lane == leader) atomicAdd(&cnt[id], __popc(m));
        }
    }
    __syncthreads();
    if (t == 0) {
        int s = 0;
        for (int j = 0; j < NDEP; ++j) { off[j] = s; s += cnt[j]; }
        off[NDEP] = s;
        for (int j = 0; j <= NDEP; ++j) g_dep_off[l][j] = off[j];
    }
    __syncthreads();
    if (t < NDEP) cnt[t] = off[t];
    __syncthreads();
    for (int it = 0; it < iters; ++it) {
        int i = it * blockDim.x + t;
        bool valid = (i < n);
        unsigned active = __ballot_sync(0xffffffffu, valid);
        if (valid) {
            int id = ids[cs + i];
            unsigned m = __match_any_sync(active, id);
            int leader = __ffs(m) - 1;
            int prior = __popc(m & ((1u << lane) - 1u));
            int basep = 0;
            if (lane == leader) basep = atomicAdd(&cnt[id], __popc(m));
            basep = __shfl_sync(active, basep, leader);
            g_dep_perm[cs + basep + prior] = cs + i;  // global child index
        }
    }
}

// ---------------------------------------------------------------------------
// Big grouped GEMM: BM=128 rows x 128 cols, full K=128 in SMEM.
// 256 threads, 8x8 register tile; rows = ty + 16*i, cols = tx + 16*q
// (conflict-free LDS: sA stride 132, sW row-major).
// ---------------------------------------------------------------------------
#define SMEM_BIG ((16384 + 128 * 132) * 4)
#define SMEM_NAR ((16384 + 16 * 132) * 4)

__global__ __launch_bounds__(256, 1)
void gemm_pos(const float* __restrict__ emb, const float* __restrict__ W,
              const float* __restrict__ bias) {
    int j = blockIdx.y;
    int g0 = g_pos_off[j], g1 = g_pos_off[j + 1];
    int base = g0 + blockIdx.x * 128;
    if (base >= g1) return;
    int mc = min(128, g1 - base);
    extern __shared__ float sm[];
    float* sW = sm;             // 128*128
    float* sA = sm + 16384;     // 128*132
    __shared__ int sNode[128];
    int t = threadIdx.x;
    if (t < 128) sNode[t] = g_pos_perm[base + min(t, mc - 1)];
    const float4* W4 = (const float4*)(W + (size_t)j * DD * DD);
    float4* sW4 = (float4*)sW;
#pragma unroll
    for (int idx = t; idx < 4096; idx += 256) sW4[idx] = W4[idx];
    __syncthreads();
    const float4* E4 = (const float4*)emb;
    for (int idx = t; idx < 128 * 32; idx += 256) {
        int r = idx >> 5, c = idx & 31;
        ((float4*)(sA + r * 132))[c] = E4[(size_t)sNode[r] * 32 + c];
    }
    __syncthreads();
    int tx = t & 15, ty = t >> 4;
    float acc[8][8];
#pragma unroll
    for (int i = 0; i < 8; ++i)
#pragma unroll
        for (int q = 0; q < 8; ++q) acc[i][q] = 0.f;
#pragma unroll 4
    for (int k = 0; k < DD; ++k) {
        float rA[8], rB[8];
#pragma unroll
        for (int i = 0; i < 8; ++i) rA[i] = sA[(ty + 16 * i) * 132 + k];
#pragma unroll
        for (int q = 0; q < 8; ++q) rB[q] = sW[k * 128 + tx + 16 * q];
#pragma unroll
        for (int i = 0; i < 8; ++i)
#pragma unroll
            for (int q = 0; q < 8; ++q) acc[i][q] += rA[i] * rB[q];
    }
    float bv[8];
#pragma unroll
    for (int q = 0; q < 8; ++q) bv[q] = bias[j * DD + tx + 16 * q];
#pragma unroll
    for (int i = 0; i < 8; ++i) {
        int node = sNode[ty + 16 * i];
        float* outp = g_xz + (size_t)node * DD;
#pragma unroll
        for (int q = 0; q < 8; ++q) {
            float v = fmaxf(acc[i][q] + bv[q], 0.f);
            outp[tx + 16 * q] = v;
        }
    }
}

__global__ __launch_bounds__(256, 1)
void gemm_dep_big(const float* __restrict__ W, const float* __restrict__ bias,
                  int l, int cs, int parentBase) {
    int j = blockIdx.y;
    int g0 = g_dep_off[l][j], g1 = g_dep_off[l][j + 1];
    int base = g0 + blockIdx.x * 128;
    if (base >= g1) return;
    int mc = min(128, g1 - base);
    extern __shared__ float sm[];
    float* sW = sm;
    float* sA = sm + 16384;
    __shared__ int sNode[128];
    int t = threadIdx.x;
    if (t < 128) sNode[t] = g_dep_perm[cs + base + min(t, mc - 1)];
    const float4* W4 = (const float4*)(W + (size_t)j * DD * DD);
    float4* sW4 = (float4*)sW;
#pragma unroll
    for (int idx = t; idx < 4096; idx += 256) sW4[idx] = W4[idx];
    __syncthreads();
    const float4* Z4 = (const float4*)g_xz;
    for (int idx = t; idx < 128 * 32; idx += 256) {
        int r = idx >> 5, c = idx & 31;
        ((float4*)(sA + r * 132))[c] = Z4[(size_t)sNode[r] * 32 + c];
    }
    __syncthreads();
    int tx = t & 15, ty = t >> 4;
    float acc[8][8];
#pragma unroll
    for (int i = 0; i < 8; ++i)
#pragma unroll
        for (int q = 0; q < 8; ++q) acc[i][q] = 0.f;
#pragma unroll 4
    for (int k = 0; k < DD; ++k) {
        float rA[8], rB[8];
#pragma unroll
        for (int i = 0; i < 8; ++i) rA[i] = sA[(ty + 16 * i) * 132 + k];
#pragma unroll
        for (int q = 0; q < 8; ++q) rB[q] = sW[k * 128 + tx + 16 * q];
#pragma unroll
        for (int i = 0; i < 8; ++i)
#pragma unroll
            for (int q = 0; q < 8; ++q) acc[i][q] += rA[i] * rB[q];
    }
    float bv[8];
#pragma unroll
    for (int q = 0; q < 8; ++q) bv[q] = bias[j * DD + tx + 16 * q];
#pragma unroll
    for (int i = 0; i < 8; ++i) {
        int node = sNode[ty + 16 * i];
        int parent = parentBase + ((node - cs) >> 2);
        int* outp = (int*)(g_xz + (size_t)parent * DD);
#pragma unroll
        for (int q = 0; q < 8; ++q) {
            float v = fmaxf(acc[i][q] + bv[q], 0.f);
            // all values post-ReLU >= 0: int compare == float compare
            atomicMax(outp + tx + 16 * q, __float_as_int(v));
        }
    }
}

// Narrow tile (BM=16) for small levels: avoids the full-tile latency floor.
__global__ __launch_bounds__(256, 2)
void gemm_dep_narrow(const float* __restrict__ W, const float* __restrict__ bias,
                     int l, int cs, int parentBase) {
    int j = blockIdx.y;
    int g0 = g_dep_off[l][j], g1 = g_dep_off[l][j + 1];
    int base = g0 + blockIdx.x * 16;
    if (base >= g1) return;
    int mc = min(16, g1 - base);
    extern __shared__ float sm[];
    float* sW = sm;            // 128*128
    float* sA = sm + 16384;    // 16*132
    __shared__ int sNode[16];
    int t = threadIdx.x;
    if (t < 16) sNode[t] = g_dep_perm[cs + base + min(t, mc - 1)];
    const float4* W4 = (const float4*)(W + (size_t)j * DD * DD);
    float4* sW4 = (float4*)sW;
#pragma unroll
    for (int idx = t; idx < 4096; idx += 256) sW4[idx] = W4[idx];
    __syncthreads();
    const float4* Z4 = (const float4*)g_xz;
    for (int idx = t; idx < 16 * 32; idx += 256) {
        int r = idx >> 5, c = idx & 31;
        ((float4*)(sA + r * 132))[c] = Z4[(size_t)sNode[r] * 32 + c];
    }
    __syncthreads();
    int tx = t & 15, ty = t >> 4;     // one row per ty, 8 cols per thread
    float acc[8];
#pragma unroll
    for (int q = 0; q < 8; ++q) acc[q] = 0.f;
#pragma unroll 4
    for (int k = 0; k < DD; ++k) {
        float rA = sA[ty * 132 + k];
#pragma unroll
        for (int q = 0; q < 8; ++q) acc[q] += rA * sW[k * 128 + tx + 16 * q];
    }
    int node = sNode[ty];
    int parent = parentBase + ((node - cs) >> 2);
    int* outp = (int*)(g_xz + (size_t)parent * DD);
#pragma unroll
    for (int q = 0; q < 8; ++q) {
        float v = fmaxf(acc[q] + bias[j * DD + tx + 16 * q], 0.f);
        atomicMax(outp + tx + 16 * q, __float_as_int(v));
    }
}

__global__ void copy_out_kernel(float* __restrict__ out) {
    out[threadIdx.x] = g_xz[threadIdx.x];   // root node 0
}

// ---------------------------------------------------------------------------
extern "C" void kernel_launch(void* const* d_in, const int* in_sizes, int n_in,
                              void* d_out, int out_size) {
    const float* emb     = (const float*)d_in[0];
    const int*   pos_ids = (const int*)d_in[1];
    const int*   dep_ids = (const int*)d_in[2];
    const float* pos_W   = (const float*)d_in[3];
    const float* pos_b   = (const float*)d_in[4];
    const float* dep_W   = (const float*)d_in[5];
    const float* dep_b   = (const float*)d_in[6];

    cudaFuncSetAttribute(gemm_pos,        cudaFuncAttributeMaxDynamicSharedMemorySize, SMEM_BIG);
    cudaFuncSetAttribute(gemm_dep_big,    cudaFuncAttributeMaxDynamicSharedMemorySize, SMEM_BIG);
    cudaFuncSetAttribute(gemm_dep_narrow, cudaFuncAttributeMaxDynamicSharedMemorySize, SMEM_NAR);

    group_pos_kernel<<<1, 1024>>>(pos_ids);
    group_dep_kernel<<<7, 512>>>(dep_ids);

    gemm_pos<<<dim3((NN + 127) / 128, NPOS), 256, SMEM_BIG>>>(emb, pos_W, pos_b);

    for (int l = 6; l >= 0; --l) {
        int cs  = ((1 << (2 * (l + 1))) - 1) / 3;   // child level start
        int pb  = ((1 << (2 * l)) - 1) / 3;         // parent level start
        int nch = 1 << (2 * (l + 1));
        if (l == 6) {
            gemm_dep_big<<<dim3((nch + 127) / 128, NDEP), 256, SMEM_BIG>>>(
                dep_W, dep_b, l, cs, pb);
        } else {
            gemm_dep_narrow<<<dim3((nch + 15) / 16, NDEP), 256, SMEM_NAR>>>(
                dep_W, dep_b, l, cs, pb);
        }
    }
    copy_out_kernel<<<1, 128>>>((float*)d_out);
}

// round 2
// speedup vs baseline: 1.7044x; 1.7044x over previous
#include <cuda_runtime.h>
#include <cuda_bf16.h>

#define DD   128
#define NN   21845          // (4^8 - 1) / 3
#define NPOS 18
#define NDEP 46
#define CS6  5461           // level_start(7)
#define PB6  1365           // level_start(6)

__host__ __device__ __forceinline__ int lvl_start(int l) {
    return ((1 << (2 * l)) - 1) / 3;
}

// persistent scratch (device globals: allocation-free)
__device__ float g_xz[NN * DD];            // x, then z in-place per level
__device__ float g_u[16384 * DD];          // level-6 child outputs (8MB)
__device__ int   g_pos_perm[NN];
__device__ int   g_pos_off[NPOS + 1];
__device__ int   g_pos_tg[384], g_pos_tb[384];
__device__ int   g_pos_nt;
__device__ int   g_dep_perm[NN];           // global child indices, grouped per level
__device__ int   g_dep_off[7][NDEP + 1];
__device__ int   g_dep_tg[7][320], g_dep_tb[7][320];
__device__ int   g_dep_nt[7];

// ---------------------------------------------------------------------------
// Grouping + tile tables: one launch, 8 blocks (0=pos, 1..7 = dep level b-1)
// ---------------------------------------------------------------------------
__global__ void group_kernel(const int* __restrict__ pos_ids,
                             const int* __restrict__ dep_ids) {
    __shared__ int cnt[NDEP];
    __shared__ int off[NDEP + 1];
    int t = threadIdx.x, lane = t & 31;
    const int* ids; int n, ng, base, BM;
    int *perm, *goff, *tg, *tb, *nt_out;
    if (blockIdx.x == 0) {
        ids = pos_ids; n = NN; ng = NPOS; base = 0; BM = 64;
        perm = g_pos_perm; goff = g_pos_off;
        tg = g_pos_tg; tb = g_pos_tb; nt_out = &g_pos_nt;
    } else {
        int l = blockIdx.x - 1;
        base = lvl_start(l + 1); n = 1 << (2 * (l + 1)); ng = NDEP;
        BM = (l == 6) ? 64 : 16;
        ids = dep_ids + base; perm = g_dep_perm + base; goff = g_dep_off[l];
        tg = g_dep_tg[l]; tb = g_dep_tb[l]; nt_out = &g_dep_nt[l];
    }
    if (t < ng) cnt[t] = 0;
    __syncthreads();
    for (int i0 = 0; i0 < n; i0 += blockDim.x) {
        int i = i0 + t; bool v = (i < n);
        unsigned act = __ballot_sync(0xffffffffu, v);
        if (v) {
            int id = ids[i];
            unsigned m = __match_any_sync(act, id);
            if (lane == __ffs(m) - 1) atomicAdd(&cnt[id], __popc(m));
        }
    }
    __syncthreads();
    if (t == 0) {
        int s = 0;
        for (int j = 0; j < ng; ++j) { off[j] = s; s += cnt[j]; }
        off[ng] = s;
        int nt = 0;
        for (int j = 0; j < ng; ++j) {
            int c = off[j + 1] - off[j];
            for (int b = 0; b < c; b += BM) { tg[nt] = j; tb[nt] = off[j] + b; ++nt; }
        }
        *nt_out = nt;
        for (int j = 0; j <= ng; ++j) goff[j] = off[j];
    }
    __syncthreads();
    if (t < ng) cnt[t] = off[t];   // cursors
    __syncthreads();
    for (int i0 = 0; i0 < n; i0 += blockDim.x) {
        int i = i0 + t; bool v = (i < n);
        unsigned act = __ballot_sync(0xffffffffu, v);
        if (v) {
            int id = ids[i];
            unsigned m = __match_any_sync(act, id);
            int leader = __ffs(m) - 1;
            int prior = __popc(m & ((1u << lane) - 1u));
            int bp = 0;
            if (lane == leader) bp = atomicAdd(&cnt[id], __popc(m));
            bp = __shfl_sync(act, bp, leader);
            perm[bp + prior] = base + i;   // global node index
        }
    }
}

// ---------------------------------------------------------------------------
// Big grouped GEMM: BM=64 x BN=128, full K=128 in smem, 256 thr, 8x4 reg tile.
// cols = 4*tx + q  (LDS.128 on W, float4 epilogue)   smem = 96KB -> 2 CTA/SM
// ---------------------------------------------------------------------------
#define SMEM_BIG ((16384 + 64 * 128) * 4)

#define GEMM_CORE()                                                          \
    int tx = t & 31, ty = t >> 5;                                            \
    float acc[8][4];                                                         \
    _Pragma("unroll") for (int i = 0; i < 8; ++i)                            \
        _Pragma("unroll") for (int q = 0; q < 4; ++q) acc[i][q] = 0.f;       \
    _Pragma("unroll 2") for (int k4 = 0; k4 < 32; ++k4) {                    \
        float4 a4[8], b4[4];                                                 \
        _Pragma("unroll") for (int i = 0; i < 8; ++i)                        \
            a4[i] = *(const float4*)&sA[(ty + 8 * i) * 128 + 4 * k4];        \
        _Pragma("unroll") for (int kk = 0; kk < 4; ++kk)                     \
            b4[kk] = *(const float4*)&sW[(4 * k4 + kk) * 128 + 4 * tx];      \
        _Pragma("unroll") for (int i = 0; i < 8; ++i) {                      \
            acc[i][0] += a4[i].x * b4[0].x; acc[i][1] += a4[i].x * b4[0].y;  \
            acc[i][2] += a4[i].x * b4[0].z; acc[i][3] += a4[i].x * b4[0].w;  \
            acc[i][0] += a4[i].y * b4[1].x; acc[i][1] += a4[i].y * b4[1].y;  \
            acc[i][2] += a4[i].y * b4[1].z; acc[i][3] += a4[i].y * b4[1].w;  \
            acc[i][0] += a4[i].z * b4[2].x; acc[i][1] += a4[i].z * b4[2].y;  \
            acc[i][2] += a4[i].z * b4[2].z; acc[i][3] += a4[i].z * b4[2].w;  \
            acc[i][0] += a4[i].w * b4[3].x; acc[i][1] += a4[i].w * b4[3].y;  \
            acc[i][2] += a4[i].w * b4[3].z; acc[i][3] += a4[i].w * b4[3].w;  \
        }                                                                    \
    }

__global__ __launch_bounds__(256, 2)
void gemm_pos(const float* __restrict__ emb, const float* __restrict__ W,
              const float* __restrict__ bias) {
    int tile = blockIdx.x;
    if (tile >= g_pos_nt) return;
    int j = g_pos_tg[tile], b0 = g_pos_tb[tile];
    int mc = g_pos_off[j + 1] - b0; if (mc > 64) mc = 64;
    extern __shared__ float sm[];
    float* sW = sm;            // 128x128
    float* sA = sm + 16384;    // 64x128
    __shared__ int sNode[64];
    int t = threadIdx.x;
    if (t < 64) sNode[t] = g_pos_perm[b0 + min(t, mc - 1)];
    const float4* W4 = (const float4*)(W + (size_t)j * 16384);
    float4* sW4 = (float4*)sW;
#pragma unroll
    for (int i = 0; i < 16; ++i) sW4[t + 256 * i] = W4[t + 256 * i];
    __syncthreads();
    const float4* E4 = (const float4*)emb;
#pragma unroll
    for (int i = 0; i < 8; ++i) {
        int idx = t + 256 * i; int r = idx >> 5, c = idx & 31;
        ((float4*)(sA + r * 128))[c] = E4[(size_t)sNode[r] * 32 + c];
    }
    __syncthreads();
    GEMM_CORE()
    float4 bv = *(const float4*)&bias[j * 128 + 4 * tx];
#pragma unroll
    for (int i = 0; i < 8; ++i) {
        int node = sNode[ty + 8 * i];
        float4 o;
        o.x = fmaxf(acc[i][0] + bv.x, 0.f);
        o.y = fmaxf(acc[i][1] + bv.y, 0.f);
        o.z = fmaxf(acc[i][2] + bv.z, 0.f);
        o.w = fmaxf(acc[i][3] + bv.w, 0.f);
        *(float4*)&g_xz[(size_t)node * 128 + 4 * tx] = o;
    }
}

__global__ __launch_bounds__(256, 2)
void gemm_dep6(const float* __restrict__ W, const float* __restrict__ bias) {
    int tile = blockIdx.x;
    if (tile >= g_dep_nt[6]) return;
    int j = g_dep_tg[6][tile], b0 = g_dep_tb[6][tile];
    int mc = g_dep_off[6][j + 1] - b0; if (mc > 64) mc = 64;
    extern __shared__ float sm[];
    float* sW = sm;
    float* sA = sm + 16384;
    __shared__ int sNode[64];
    int t = threadIdx.x;
    if (t < 64) sNode[t] = g_dep_perm[CS6 + b0 + min(t, mc - 1)];
    const float4* W4 = (const float4*)(W + (size_t)j * 16384);
    float4* sW4 = (float4*)sW;
#pragma unroll
    for (int i = 0; i < 16; ++i) sW4[t + 256 * i] = W4[t + 256 * i];
    __syncthreads();
    const float4* Z4 = (const float4*)g_xz;
#pragma unroll
    for (int i = 0; i < 8; ++i) {
        int idx = t + 256 * i; int r = idx >> 5, c = idx & 31;
        ((float4*)(sA + r * 128))[c] = Z4[(size_t)sNode[r] * 32 + c];
    }
    __syncthreads();
    GEMM_CORE()
    float4 bv = *(const float4*)&bias[j * 128 + 4 * tx];
#pragma unroll
    for (int i = 0; i < 8; ++i) {
        int node = sNode[ty + 8 * i];
        float4 o;
        o.x = fmaxf(acc[i][0] + bv.x, 0.f);
        o.y = fmaxf(acc[i][1] + bv.y, 0.f);
        o.z = fmaxf(acc[i][2] + bv.z, 0.f);
        o.w = fmaxf(acc[i][3] + bv.w, 0.f);
        *(float4*)&g_u[(size_t)(node - CS6) * 128 + 4 * tx] = o;
    }
}

// z[parent] = max(x[parent], max over 4 children of u)
__global__ void reduce6_kernel() {
    int idx = blockIdx.x * blockDim.x + threadIdx.x;  // 4096 parents * 32 f4
    int p = idx >> 5, c = idx & 31;
    const float4* u = (const float4*)g_u;
    float4 a = u[(size_t)(4 * p + 0) * 32 + c];
    float4 b = u[(size_t)(4 * p + 1) * 32 + c];
    float4 d = u[(size_t)(4 * p + 2) * 32 + c];
    float4 e = u[(size_t)(4 * p + 3) * 32 + c];
    float4* z = (float4*)&g_xz[(size_t)(PB6 + p) * 128];
    float4 x = z[c];
    x.x = fmaxf(x.x, fmaxf(fmaxf(a.x, b.x), fmaxf(d.x, e.x)));
    x.y = fmaxf(x.y, fmaxf(fmaxf(a.y, b.y), fmaxf(d.y, e.y)));
    x.z = fmaxf(x.z, fmaxf(fmaxf(a.z, b.z), fmaxf(d.z, e.z)));
    x.w = fmaxf(x.w, fmaxf(fmaxf(a.w, b.w), fmaxf(d.w, e.w)));
    z[c] = x;
}

// ---------------------------------------------------------------------------
// Narrow tile for small levels: 16 rows x 32 cols per block, 128 threads.
// Each thread: 1 row x 4 cols (LDS.128 on W slice).  atomicMax into parent.
// ---------------------------------------------------------------------------
__global__ __launch_bounds__(128)
void gemm_dep_narrow(const float* __restrict__ W, const float* __restrict__ bias,
                     int l, int cs, int pb) {
    int tile = blockIdx.x;
    if (tile >= g_dep_nt[l]) return;
    int j = g_dep_tg[l][tile], b0 = g_dep_tb[l][tile];
    int mc = g_dep_off[l][j + 1] - b0; if (mc > 16) mc = 16;
    int c0 = blockIdx.y * 32;
    __shared__ __align__(16) float sW[128 * 36];  // [k][36] slice of 32 cols
    __shared__ __align__(16) float sA[16 * 128];
    __shared__ int sNode[16];
    int t = threadIdx.x;
    if (t < 16) sNode[t] = g_dep_perm[cs + b0 + min(t, mc - 1)];
#pragma unroll
    for (int i = 0; i < 8; ++i) {
        int idx = t + 128 * i; int k = idx >> 3, c4 = idx & 7;
        *(float4*)&sW[k * 36 + 4 * c4] =
            *(const float4*)&W[(size_t)j * 16384 + k * 128 + c0 + 4 * c4];
    }
    __syncthreads();
    const float4* Z4 = (const float4*)g_xz;
#pragma unroll
    for (int i = 0; i < 4; ++i) {
        int idx = t + 128 * i; int r = idx >> 5, c = idx & 31;
        ((float4*)(sA + r * 128))[c] = Z4[(size_t)sNode[r] * 32 + c];
    }
    __syncthreads();
    int r = t >> 3, x8 = t & 7;
    float a0 = 0.f, a1 = 0.f, a2 = 0.f, a3 = 0.f;
#pragma unroll 4
    for (int k = 0; k < 128; ++k) {
        float a = sA[r * 128 + k];
        float4 w = *(const float4*)&sW[k * 36 + 4 * x8];
        a0 += a * w.x; a1 += a * w.y; a2 += a * w.z; a3 += a * w.w;
    }
    int node = sNode[r];
    int parent = pb + ((node - cs) >> 2);
    int col = c0 + 4 * x8;
    float4 bv = *(const float4*)&bias[j * 128 + col];
    int* zp = (int*)&g_xz[(size_t)parent * 128 + col];
    // post-ReLU values >= 0: int ordering == float ordering
    atomicMax(zp + 0, __float_as_int(fmaxf(a0 + bv.x, 0.f)));
    atomicMax(zp + 1, __float_as_int(fmaxf(a1 + bv.y, 0.f)));
    atomicMax(zp + 2, __float_as_int(fmaxf(a2 + bv.z, 0.f)));
    atomicMax(zp + 3, __float_as_int(fmaxf(a3 + bv.w, 0.f)));
}

__global__ void copy_out_kernel(float* __restrict__ out) {
    out[threadIdx.x] = g_xz[threadIdx.x];   // root node 0
}

// ---------------------------------------------------------------------------
extern "C" void kernel_launch(void* const* d_in, const int* in_sizes, int n_in,
                              void* d_out, int out_size) {
    const float* emb     = (const float*)d_in[0];
    const int*   pos_ids = (const int*)d_in[1];
    const int*   dep_ids = (const int*)d_in[2];
    const float* pos_W   = (const float*)d_in[3];
    const float* pos_b   = (const float*)d_in[4];
    const float* dep_W   = (const float*)d_in[5];
    const float* dep_b   = (const float*)d_in[6];

    cudaFuncSetAttribute(gemm_pos,  cudaFuncAttributeMaxDynamicSharedMemorySize, SMEM_BIG);
    cudaFuncSetAttribute(gemm_dep6, cudaFuncAttributeMaxDynamicSharedMemorySize, SMEM_BIG);

    group_kernel<<<8, 512>>>(pos_ids, dep_ids);

    // pos: tiles <= 18 + 21845/64 = 359
    gemm_pos<<<360, 256, SMEM_BIG>>>(emb, pos_W, pos_b);

    // level 6: tiles <= 46 + 16384/64 = 302
    gemm_dep6<<<302, 256, SMEM_BIG>>>(dep_W, dep_b);
    reduce6_kernel<<<512, 256>>>();

    for (int l = 5; l >= 0; --l) {
        int cs  = lvl_start(l + 1);
        int pb  = lvl_start(l);
        int nch = 1 << (2 * (l + 1));
        int bound = ((nch < NDEP) ? nch : NDEP) + nch / 16;
        gemm_dep_narrow<<<dim3(bound, 4), 128>>>(dep_W, dep_b, l, cs, pb);
    }
    copy_out_kernel<<<1, 128>>>((float*)d_out);
}